// round 6
// baseline (speedup 1.0000x reference)
#include <cuda_runtime.h>
#include <math.h>
#include <stdint.h>

#define B_ 2
#define L_ 4096
#define H_ 8
#define D_ 64
#define U_ 45
#define BH_ (B_*H_)

// ---------------- scratch (static device allocations only) ----------------
__device__ float g_M[BH_*L_];                      // 256 KB  M scores
__device__ int   g_top[BH_*U_];                    // top-45 indices (sorted desc)
__device__ float g_S[(size_t)BH_*U_*L_];           // 11.8 MB  scores -> probs
__device__ float g_part[(size_t)BH_*64*U_*D_];     // 11.8 MB  PV partials

// ---------------- threefry2x32 (exact JAX replication) ----------------
__host__ __device__ __forceinline__ uint32_t rotl32(uint32_t x, int d) {
    return (x << d) | (x >> (32 - d));
}

__host__ __device__ __forceinline__ void tf2x32(uint32_t k0, uint32_t k1,
                                                uint32_t x0, uint32_t x1,
                                                uint32_t& o0, uint32_t& o1) {
    uint32_t ks2 = k0 ^ k1 ^ 0x1BD11BDAu;
    x0 += k0; x1 += k1;
#define RND(r) { x0 += x1; x1 = rotl32(x1, (r)); x1 ^= x0; }
    RND(13) RND(15) RND(26) RND(6)   x0 += k1;  x1 += ks2 + 1u;
    RND(17) RND(29) RND(16) RND(24)  x0 += ks2; x1 += k0  + 2u;
    RND(13) RND(15) RND(26) RND(6)   x0 += k0;  x1 += k1  + 3u;
    RND(17) RND(29) RND(16) RND(24)  x0 += k1;  x1 += ks2 + 4u;
    RND(13) RND(15) RND(26) RND(6)   x0 += ks2; x1 += k0  + 5u;
#undef RND
    o0 = x0; o1 = x1;
}

// ---------------- Kernel B: sampled M scores ----------------
// One block per query q (all 16 (b,h) pairs). 768 threads.
// M[bh][q] = max_s(Q[bh,q]·K[bh,idx[q,s]]) - sum_s(...)/L
__global__ __launch_bounds__(768) void sample_m_kernel(
    const float* __restrict__ Q, const float* __restrict__ K,
    uint32_t k2a, uint32_t k2b)
{
    int q = blockIdx.x;
    int t = threadIdx.x;
    __shared__ __align__(16) float qsm[BH_ * D_];   // 16 q-rows (one per bh)
    __shared__ int   idxs[U_];
    __shared__ float dots[BH_ * U_];

    // partitionable-mode random_bits: element j -> threefry(k2; hi=0, lo=j),
    // 32-bit value = o0 ^ o1; randint span=4096 (pow2) -> value & 4095
    if (t < U_) {
        int j = q * U_ + t;
        uint32_t o0, o1;
        tf2x32(k2a, k2b, 0u, (uint32_t)j, o0, o1);
        idxs[t] = (int)((o0 ^ o1) & (L_ - 1));
    }
    // load Q rows for all 16 bh
    for (int i = t; i < BH_ * D_; i += 768) {
        int bh = i >> 6, d = i & 63;
        int b = bh >> 3, h = bh & 7;
        qsm[i] = Q[((b * L_ + q) * H_ + h) * D_ + d];
    }
    __syncthreads();

    if (t < BH_ * U_) {
        int bh = t / U_, s = t % U_;
        int b = bh >> 3, h = bh & 7;
        int kr = idxs[s];
        const float4* kp = reinterpret_cast<const float4*>(K + ((b * L_ + kr) * H_ + h) * D_);
        const float4* qp = reinterpret_cast<const float4*>(qsm + bh * D_);
        float acc = 0.f;
#pragma unroll
        for (int i = 0; i < 16; i++) {
            float4 kv = kp[i]; float4 qv = qp[i];
            acc += kv.x * qv.x + kv.y * qv.y + kv.z * qv.z + kv.w * qv.w;
        }
        dots[t] = acc;
    }
    __syncthreads();

    if (t < BH_) {
        float m = -INFINITY, sum = 0.f;
        for (int s = 0; s < U_; s++) {
            float v = dots[t * U_ + s];
            m = fmaxf(m, v);
            sum += v;
        }
        g_M[t * L_ + q] = m - sum * (1.0f / (float)L_);
    }
}

// ---------------- Kernel C: top-45 per (b,h), sorted desc, min-index ties ----------------
__global__ __launch_bounds__(1024) void topk_kernel()
{
    int bh = blockIdx.x;
    int tid = threadIdx.x, lane = tid & 31, wid = tid >> 5;
    __shared__ float sv[L_];
    __shared__ float wv[32];
    __shared__ int   wi[32];

    for (int i = tid; i < L_; i += 1024) sv[i] = g_M[bh * L_ + i];
    __syncthreads();

    for (int it = 0; it < U_; it++) {
        float bv = -INFINITY; int bi = 0x7fffffff;
        for (int i = tid; i < L_; i += 1024) {
            float v = sv[i];
            if (v > bv || (v == bv && i < bi)) { bv = v; bi = i; }
        }
#pragma unroll
        for (int o = 16; o > 0; o >>= 1) {
            float ov = __shfl_down_sync(0xffffffffu, bv, o);
            int   oi = __shfl_down_sync(0xffffffffu, bi, o);
            if (ov > bv || (ov == bv && oi < bi)) { bv = ov; bi = oi; }
        }
        if (lane == 0) { wv[wid] = bv; wi[wid] = bi; }
        __syncthreads();
        if (wid == 0) {
            bv = wv[lane]; bi = wi[lane];
#pragma unroll
            for (int o = 16; o > 0; o >>= 1) {
                float ov = __shfl_down_sync(0xffffffffu, bv, o);
                int   oi = __shfl_down_sync(0xffffffffu, bi, o);
                if (ov > bv || (ov == bv && oi < bi)) { bv = ov; bi = oi; }
            }
            if (lane == 0) { g_top[bh * U_ + it] = bi; sv[bi] = -INFINITY; }
        }
        __syncthreads();
    }
}

// ---------------- Kernel D1: scores for selected queries ----------------
// grid (16 bh, 16 key-chunks of 256). Thread = one key, 45 accumulators.
__global__ __launch_bounds__(256) void scores_kernel(
    const float* __restrict__ Q, const float* __restrict__ K,
    const int* __restrict__ mask)
{
    int bh = blockIdx.x, chunk = blockIdx.y;
    int b = bh >> 3, h = bh & 7;
    int tid = threadIdx.x;
    __shared__ __align__(16) float qsm[U_ * D_];
    __shared__ int qidx[U_];

    if (tid < U_) qidx[tid] = g_top[bh * U_ + tid];
    __syncthreads();
    for (int i = tid; i < U_ * D_; i += 256) {
        int u = i >> 6, d = i & 63;
        qsm[i] = Q[((b * L_ + qidx[u]) * H_ + h) * D_ + d];
    }
    __syncthreads();

    int k = chunk * 256 + tid;
    const float4* kp  = reinterpret_cast<const float4*>(K + ((b * L_ + k) * H_ + h) * D_);
    const float4* qp4 = reinterpret_cast<const float4*>(qsm);

    float acc[U_];
#pragma unroll
    for (int u = 0; u < U_; u++) acc[u] = 0.f;

    for (int dv = 0; dv < 16; dv++) {
        float4 kv = kp[dv];
#pragma unroll
        for (int u = 0; u < U_; u++) {
            float4 qv = qp4[u * 16 + dv];
            acc[u] += kv.x * qv.x + kv.y * qv.y + kv.z * qv.z + kv.w * qv.w;
        }
    }

    bool valid = (mask[b * L_ + k] != 0);
#pragma unroll
    for (int u = 0; u < U_; u++) {
        float s = acc[u] * 0.125f;   // 1/sqrt(64)
        g_S[((size_t)(bh * U_ + u)) * L_ + k] = valid ? s : -INFINITY;
    }
}

// ---------------- Kernel D2: softmax per selected row ----------------
__global__ __launch_bounds__(256) void softmax_kernel()
{
    int row = blockIdx.x;             // bh*45+u
    int tid = threadIdx.x, lane = tid & 31, wid = tid >> 5;
    float* S = g_S + (size_t)row * L_;
    __shared__ float red[8];
    __shared__ float bm, bs;

    float m = -INFINITY;
    for (int i = tid; i < L_; i += 256) m = fmaxf(m, S[i]);
#pragma unroll
    for (int o = 16; o > 0; o >>= 1) m = fmaxf(m, __shfl_xor_sync(0xffffffffu, m, o));
    if (lane == 0) red[wid] = m;
    __syncthreads();
    if (tid == 0) {
        float mm = red[0];
        for (int i = 1; i < 8; i++) mm = fmaxf(mm, red[i]);
        bm = mm;
    }
    __syncthreads();
    float M = bm, sum = 0.f;
    for (int i = tid; i < L_; i += 256) { float e = expf(S[i] - M); S[i] = e; sum += e; }
#pragma unroll
    for (int o = 16; o > 0; o >>= 1) sum += __shfl_xor_sync(0xffffffffu, sum, o);
    if (lane == 0) red[wid] = sum;
    __syncthreads();
    if (tid == 0) {
        float t = 0.f;
        for (int i = 0; i < 8; i++) t += red[i];
        bs = t;
    }
    __syncthreads();
    float inv = 1.0f / bs;
    for (int i = tid; i < L_; i += 256) S[i] *= inv;
}

// ---------------- Kernel D3: PV partials ----------------
// grid (16 bh, 64 key-chunks of 64). 64 threads = one output dim d each.
__global__ __launch_bounds__(64) void pv_kernel(const float* __restrict__ V)
{
    int bh = blockIdx.x, chunk = blockIdx.y;
    int b = bh >> 3, h = bh & 7;
    int tid = threadIdx.x;            // = d
    int k0 = chunk * 64;
    __shared__ float ssm[U_ * 64];

    for (int i = tid; i < U_ * 64; i += 64) {
        int u = i >> 6, kk = i & 63;
        ssm[i] = g_S[((size_t)(bh * U_ + u)) * L_ + k0 + kk];
    }
    __syncthreads();

    float acc[U_];
#pragma unroll
    for (int u = 0; u < U_; u++) acc[u] = 0.f;

    for (int kk = 0; kk < 64; kk++) {
        float v = V[((b * L_ + k0 + kk) * H_ + h) * D_ + tid];
#pragma unroll
        for (int u = 0; u < U_; u++) acc[u] += ssm[u * 64 + kk] * v;
    }
#pragma unroll
    for (int u = 0; u < U_; u++)
        g_part[(((size_t)bh * 64 + chunk) * U_ + u) * D_ + tid] = acc[u];
}

// ---------------- Kernel D4: chunk reduction + output transpose ----------------
__global__ __launch_bounds__(64) void reduce_kernel(float* __restrict__ out)
{
    int blk = blockIdx.x;             // bh*45+u
    int bh = blk / U_, u = blk % U_;
    int b = bh >> 3, h = bh & 7;
    int d = threadIdx.x;
    float s = 0.f;
    for (int c = 0; c < 64; c++)
        s += g_part[(((size_t)bh * 64 + c) * U_ + u) * D_ + d];
    out[((b * U_ + u) * H_ + h) * D_ + d] = s;   // (B, u, H, D)
}

// ---------------- launch ----------------
extern "C" void kernel_launch(void* const* d_in, const int* in_sizes, int n_in,
                              void* d_out, int out_size)
{
    const float* Q    = (const float*)d_in[0];
    const float* K    = (const float*)d_in[1];
    const float* V    = (const float*)d_in[2];
    const int*   mask = (const int*)d_in[3];
    float* out = (float*)d_out;

    // JAX partitionable (foldlike) split of key(1)=(0,1):
    //   child i = BOTH output words of threefry((0,1); hi=0, lo=i)
    // randint uses the SECOND child (k2) for lower_bits.
    uint32_t k2a, k2b;
    tf2x32(0u, 1u, 0u, 1u, k2a, k2b);

    sample_m_kernel<<<L_, 768>>>(Q, K, k2a, k2b);
    topk_kernel<<<BH_, 1024>>>();
    scores_kernel<<<dim3(BH_, 16), 256>>>(Q, K, mask);
    softmax_kernel<<<BH_ * U_, 256>>>();
    pv_kernel<<<dim3(BH_, 64), 64>>>(V);
    reduce_kernel<<<BH_ * U_, 64>>>(out);
}

// round 7
// speedup vs baseline: 2.0146x; 2.0146x over previous
#include <cuda_runtime.h>
#include <math.h>
#include <stdint.h>

#define B_ 2
#define L_ 4096
#define H_ 8
#define D_ 64
#define U_ 45
#define BH_ (B_*H_)
#define PV_CH 64            /* pv key-chunks */
#define PV_KS (L_/PV_CH)    /* 64 keys per chunk */

// ---------------- scratch (static device allocations only) ----------------
__device__ float g_M[BH_*L_];                        // 256 KB  M scores
__device__ int   g_top[BH_*U_];                      // top-45 indices
__device__ float g_S[(size_t)BH_*U_*L_];             // 11.8 MB  scores -> probs
__device__ float g_part[(size_t)BH_*PV_CH*U_*D_];    // 11.8 MB  PV partials

// ---------------- threefry2x32 (exact JAX replication) ----------------
__host__ __device__ __forceinline__ uint32_t rotl32(uint32_t x, int d) {
    return (x << d) | (x >> (32 - d));
}

__host__ __device__ __forceinline__ void tf2x32(uint32_t k0, uint32_t k1,
                                                uint32_t x0, uint32_t x1,
                                                uint32_t& o0, uint32_t& o1) {
    uint32_t ks2 = k0 ^ k1 ^ 0x1BD11BDAu;
    x0 += k0; x1 += k1;
#define RND(r) { x0 += x1; x1 = rotl32(x1, (r)); x1 ^= x0; }
    RND(13) RND(15) RND(26) RND(6)   x0 += k1;  x1 += ks2 + 1u;
    RND(17) RND(29) RND(16) RND(24)  x0 += ks2; x1 += k0  + 2u;
    RND(13) RND(15) RND(26) RND(6)   x0 += k0;  x1 += k1  + 3u;
    RND(17) RND(29) RND(16) RND(24)  x0 += k1;  x1 += ks2 + 4u;
    RND(13) RND(15) RND(26) RND(6)   x0 += ks2; x1 += k0  + 5u;
#undef RND
    o0 = x0; o1 = x1;
}

// ---------------- Kernel B: sampled M scores (coalesced, warp per (q,s)) ----
// Block = (q, b). For fixed (q,s,b) the 8 heads' K rows are ONE contiguous
// 2KB block; a warp loads it with 4 fully-coalesced LDG.128 and computes the
// 8 dots via butterfly shfl over 16-lane halves.
__global__ __launch_bounds__(384) void sample_m_kernel(
    const float* __restrict__ Q, const float* __restrict__ K,
    uint32_t k2a, uint32_t k2b)
{
    int q = blockIdx.x, b = blockIdx.y;
    int t = threadIdx.x, lane = t & 31, w = t >> 5;   // 12 warps
    __shared__ __align__(16) float4 qsm[128];         // Q[b,q,:,:]  512 floats
    __shared__ int   idxs[U_];
    __shared__ float dots[U_ * 8];

    // partitionable-mode random_bits: element j -> threefry(k2; 0, j), o0^o1, &4095
    if (t < U_) {
        uint32_t o0, o1;
        tf2x32(k2a, k2b, 0u, (uint32_t)(q * U_ + t), o0, o1);
        idxs[t] = (int)((o0 ^ o1) & (L_ - 1));
    }
    if (t < 128)
        qsm[t] = reinterpret_cast<const float4*>(Q)[(size_t)(b * L_ + q) * 128 + t];
    __syncthreads();

    for (int s = w; s < U_; s += 12) {
        int kr = idxs[s];
        const float4* kp = reinterpret_cast<const float4*>(K) + (size_t)(b * L_ + kr) * 128;
        // float4 j = i*32+lane -> head h = 2i + (lane>>4), d = 4*(lane&15)
        float p[4];
#pragma unroll
        for (int i = 0; i < 4; i++) {
            float4 kv = __ldg(kp + i * 32 + lane);
            float4 qv = qsm[i * 32 + lane];
            p[i] = kv.x * qv.x + kv.y * qv.y + kv.z * qv.z + kv.w * qv.w;
        }
        // reduce across the 16 lanes sharing each head
#pragma unroll
        for (int o = 1; o <= 8; o <<= 1) {
#pragma unroll
            for (int i = 0; i < 4; i++)
                p[i] += __shfl_xor_sync(0xffffffffu, p[i], o);
        }
        if ((lane & 15) == 0) {
            int hb = lane >> 4;
#pragma unroll
            for (int i = 0; i < 4; i++)
                dots[s * 8 + 2 * i + hb] = p[i];
        }
    }
    __syncthreads();

    if (t < 8) {
        float m = -INFINITY, sum = 0.f;
        for (int s = 0; s < U_; s++) {
            float v = dots[s * 8 + t];
            m = fmaxf(m, v);
            sum += v;
        }
        g_M[(b * 8 + t) * L_ + q] = m - sum * (1.0f / (float)L_);
    }
}

// ---------------- Kernel C: top-45 per (b,h), sorted desc, min-index ties ----
__global__ __launch_bounds__(1024) void topk_kernel()
{
    int bh = blockIdx.x;
    int tid = threadIdx.x, lane = tid & 31, wid = tid >> 5;
    __shared__ float sv[L_];
    __shared__ float wv[32];
    __shared__ int   wi[32];

    for (int i = tid; i < L_; i += 1024) sv[i] = g_M[bh * L_ + i];
    __syncthreads();

    for (int it = 0; it < U_; it++) {
        float bv = -INFINITY; int bi = 0x7fffffff;
        for (int i = tid; i < L_; i += 1024) {
            float v = sv[i];
            if (v > bv || (v == bv && i < bi)) { bv = v; bi = i; }
        }
#pragma unroll
        for (int o = 16; o > 0; o >>= 1) {
            float ov = __shfl_down_sync(0xffffffffu, bv, o);
            int   oi = __shfl_down_sync(0xffffffffu, bi, o);
            if (ov > bv || (ov == bv && oi < bi)) { bv = ov; bi = oi; }
        }
        if (lane == 0) { wv[wid] = bv; wi[wid] = bi; }
        __syncthreads();
        if (wid == 0) {
            bv = wv[lane]; bi = wi[lane];
#pragma unroll
            for (int o = 16; o > 0; o >>= 1) {
                float ov = __shfl_down_sync(0xffffffffu, bv, o);
                int   oi = __shfl_down_sync(0xffffffffu, bi, o);
                if (ov > bv || (ov == bv && oi < bi)) { bv = ov; bi = oi; }
            }
            if (lane == 0) { g_top[bh * U_ + it] = bi; sv[bi] = -INFINITY; }
        }
        __syncthreads();
    }
}

// ---------------- Kernel D1: scores for selected queries ----------------
__global__ __launch_bounds__(256) void scores_kernel(
    const float* __restrict__ Q, const float* __restrict__ K,
    const int* __restrict__ mask)
{
    int bh = blockIdx.x, chunk = blockIdx.y;
    int b = bh >> 3, h = bh & 7;
    int tid = threadIdx.x;
    __shared__ __align__(16) float qsm[U_ * D_];
    __shared__ int qidx[U_];

    if (tid < U_) qidx[tid] = g_top[bh * U_ + tid];
    __syncthreads();
    for (int i = tid; i < U_ * D_; i += 256) {
        int u = i >> 6, d = i & 63;
        qsm[i] = Q[((b * L_ + qidx[u]) * H_ + h) * D_ + d];
    }
    __syncthreads();

    int k = chunk * 256 + tid;
    const float4* kp  = reinterpret_cast<const float4*>(K + ((b * L_ + k) * H_ + h) * D_);
    const float4* qp4 = reinterpret_cast<const float4*>(qsm);

    float acc[U_];
#pragma unroll
    for (int u = 0; u < U_; u++) acc[u] = 0.f;

    for (int dv = 0; dv < 16; dv++) {
        float4 kv = kp[dv];
#pragma unroll
        for (int u = 0; u < U_; u++) {
            float4 qv = qp4[u * 16 + dv];
            acc[u] += kv.x * qv.x + kv.y * qv.y + kv.z * qv.z + kv.w * qv.w;
        }
    }

    bool valid = (mask[b * L_ + k] != 0);
#pragma unroll
    for (int u = 0; u < U_; u++) {
        float s = acc[u] * 0.125f;   // 1/sqrt(64)
        g_S[((size_t)(bh * U_ + u)) * L_ + k] = valid ? s : -INFINITY;
    }
}

// ---------------- Kernel D2: softmax per selected row (1 read + 1 write) ----
__global__ __launch_bounds__(512) void softmax_kernel()
{
    int row = blockIdx.x;
    int t = threadIdx.x, lane = t & 31, wid = t >> 5;   // 16 warps
    float4* S4 = reinterpret_cast<float4*>(g_S + (size_t)row * L_);  // 1024 float4
    __shared__ float red[16];

    float4 v0 = S4[t], v1 = S4[t + 512];
    float m = fmaxf(fmaxf(fmaxf(v0.x, v0.y), fmaxf(v0.z, v0.w)),
                    fmaxf(fmaxf(v1.x, v1.y), fmaxf(v1.z, v1.w)));
#pragma unroll
    for (int o = 16; o > 0; o >>= 1) m = fmaxf(m, __shfl_xor_sync(0xffffffffu, m, o));
    if (lane == 0) red[wid] = m;
    __syncthreads();
    float M = red[0];
#pragma unroll
    for (int i = 1; i < 16; i++) M = fmaxf(M, red[i]);
    __syncthreads();

    v0.x = __expf(v0.x - M); v0.y = __expf(v0.y - M);
    v0.z = __expf(v0.z - M); v0.w = __expf(v0.w - M);
    v1.x = __expf(v1.x - M); v1.y = __expf(v1.y - M);
    v1.z = __expf(v1.z - M); v1.w = __expf(v1.w - M);
    float s = v0.x + v0.y + v0.z + v0.w + v1.x + v1.y + v1.z + v1.w;
#pragma unroll
    for (int o = 16; o > 0; o >>= 1) s += __shfl_xor_sync(0xffffffffu, s, o);
    if (lane == 0) red[wid] = s;
    __syncthreads();
    float S = 0.f;
#pragma unroll
    for (int i = 0; i < 16; i++) S += red[i];

    float inv = 1.0f / S;
    v0.x *= inv; v0.y *= inv; v0.z *= inv; v0.w *= inv;
    v1.x *= inv; v1.y *= inv; v1.z *= inv; v1.w *= inv;
    S4[t] = v0; S4[t + 512] = v1;
}

// ---------------- Kernel D3: PV partials ----------------
// grid (16 bh, 64 chunks of 64 keys). 256 threads = 8 warps; warp g handles
// u in [g*6, g*6+6); every thread loops all 64 keys. Probs and V staged in smem.
__global__ __launch_bounds__(256) void pv_kernel(const float* __restrict__ V)
{
    int bh = blockIdx.x, ch = blockIdx.y;
    int b = bh >> 3, h = bh & 7;
    int t = threadIdx.x;
    int g = t >> 5;           // warp -> u-group
    int dp = t & 31;          // float2 lane: d = 2*dp
    int k0 = ch * PV_KS;
    __shared__ float ssm[U_ * PV_KS];        // 45*64 probs  (11.5 KB)
    __shared__ float vsm[PV_KS * D_];        // 64*64 V tile (16 KB)

    for (int i = t; i < U_ * PV_KS; i += 256) {
        int u = i >> 6, kk = i & 63;
        ssm[i] = g_S[((size_t)(bh * U_ + u)) * L_ + k0 + kk];
    }
    for (int i = t; i < PV_KS * D_; i += 256) {
        int kk = i >> 6, d = i & 63;
        vsm[i] = V[((b * L_ + k0 + kk) * H_ + h) * D_ + d];
    }
    __syncthreads();

    int u0 = g * 6;
    float2 acc[6];
#pragma unroll
    for (int uu = 0; uu < 6; uu++) acc[uu] = make_float2(0.f, 0.f);

    const float2* vs2 = reinterpret_cast<const float2*>(vsm);
    for (int kk = 0; kk < PV_KS; kk++) {
        float2 v = vs2[kk * 32 + dp];
#pragma unroll
        for (int uu = 0; uu < 6; uu++) {
            if (u0 + uu < U_) {
                float p = ssm[(u0 + uu) * PV_KS + kk];
                acc[uu].x += p * v.x;
                acc[uu].y += p * v.y;
            }
        }
    }

#pragma unroll
    for (int uu = 0; uu < 6; uu++) {
        if (u0 + uu < U_) {
            float2* gp = reinterpret_cast<float2*>(
                g_part + (((size_t)(bh * PV_CH) + ch) * U_ + (u0 + uu)) * D_);
            gp[dp] = acc[uu];
        }
    }
}

// ---------------- Kernel D4: chunk reduction + output transpose ----------------
__global__ __launch_bounds__(64) void reduce_kernel(float* __restrict__ out)
{
    int blk = blockIdx.x;             // bh*45+u
    int bh = blk / U_, u = blk % U_;
    int b = bh >> 3, h = bh & 7;
    int d = threadIdx.x;
    float s = 0.f;
    for (int c = 0; c < PV_CH; c++)
        s += g_part[(((size_t)(bh * PV_CH) + c) * U_ + u) * D_ + d];
    out[((b * U_ + u) * H_ + h) * D_ + d] = s;   // (B, u, H, D)
}

// ---------------- launch ----------------
extern "C" void kernel_launch(void* const* d_in, const int* in_sizes, int n_in,
                              void* d_out, int out_size)
{
    const float* Q    = (const float*)d_in[0];
    const float* K    = (const float*)d_in[1];
    const float* V    = (const float*)d_in[2];
    const int*   mask = (const int*)d_in[3];
    float* out = (float*)d_out;

    // JAX partitionable (foldlike) split of key(1)=(0,1):
    //   child i = BOTH output words of threefry((0,1); hi=0, lo=i); randint uses child 1.
    uint32_t k2a, k2b;
    tf2x32(0u, 1u, 0u, 1u, k2a, k2b);

    sample_m_kernel<<<dim3(L_, B_), 384>>>(Q, K, k2a, k2b);
    topk_kernel<<<BH_, 1024>>>();
    scores_kernel<<<dim3(BH_, 16), 256>>>(Q, K, mask);
    softmax_kernel<<<BH_ * U_, 512>>>();
    pv_kernel<<<dim3(BH_, PV_CH), 256>>>(V);
    reduce_kernel<<<BH_ * U_, 64>>>(out);
}

// round 10
// speedup vs baseline: 2.1544x; 1.0694x over previous
#include <cuda_runtime.h>
#include <math.h>
#include <stdint.h>

#define B_ 2
#define L_ 4096
#define H_ 8
#define D_ 64
#define U_ 45
#define BH_ (B_*H_)
#define FC_ 32              /* flash key-chunks */
#define FK_ 128             /* keys per chunk */
#define SP_ 132             /* padded S row (floats) */

// ---------------- scratch (static device allocations only) ----------------
__device__ float g_M[BH_*L_];                        // M scores
__device__ int   g_top[BH_*U_];                      // top-45 indices (desc order)
__device__ float g_part[(size_t)BH_*FC_*U_*D_];      // 5.9 MB PV partials
__device__ float g_mrow[BH_*FC_*U_];                 // chunk max
__device__ float g_srow[BH_*FC_*U_];                 // chunk expsum

// ---------------- threefry2x32 (exact JAX replication) ----------------
__host__ __device__ __forceinline__ uint32_t rotl32(uint32_t x, int d) {
    return (x << d) | (x >> (32 - d));
}

__host__ __device__ __forceinline__ void tf2x32(uint32_t k0, uint32_t k1,
                                                uint32_t x0, uint32_t x1,
                                                uint32_t& o0, uint32_t& o1) {
    uint32_t ks2 = k0 ^ k1 ^ 0x1BD11BDAu;
    x0 += k0; x1 += k1;
#define RND(r) { x0 += x1; x1 = rotl32(x1, (r)); x1 ^= x0; }
    RND(13) RND(15) RND(26) RND(6)   x0 += k1;  x1 += ks2 + 1u;
    RND(17) RND(29) RND(16) RND(24)  x0 += ks2; x1 += k0  + 2u;
    RND(13) RND(15) RND(26) RND(6)   x0 += k0;  x1 += k1  + 3u;
    RND(17) RND(29) RND(16) RND(24)  x0 += k1;  x1 += ks2 + 4u;
    RND(13) RND(15) RND(26) RND(6)   x0 += ks2; x1 += k0  + 5u;
#undef RND
    o0 = x0; o1 = x1;
}

// ---------------- Kernel B: sampled M scores (coalesced, warp per (q,s)) ----
__global__ __launch_bounds__(384) void sample_m_kernel(
    const float* __restrict__ Q, const float* __restrict__ K,
    uint32_t k2a, uint32_t k2b)
{
    int q = blockIdx.x, b = blockIdx.y;
    int t = threadIdx.x, lane = t & 31, w = t >> 5;   // 12 warps
    __shared__ __align__(16) float4 qsm[128];         // Q[b,q,:,:]  512 floats
    __shared__ int   idxs[U_];
    __shared__ float dots[U_ * 8];

    if (t < U_) {
        uint32_t o0, o1;
        tf2x32(k2a, k2b, 0u, (uint32_t)(q * U_ + t), o0, o1);
        idxs[t] = (int)((o0 ^ o1) & (L_ - 1));
    }
    if (t < 128)
        qsm[t] = reinterpret_cast<const float4*>(Q)[(size_t)(b * L_ + q) * 128 + t];
    __syncthreads();

    for (int s = w; s < U_; s += 12) {
        int kr = idxs[s];
        const float4* kp = reinterpret_cast<const float4*>(K) + (size_t)(b * L_ + kr) * 128;
        float p0, p1, p2, p3;
        {
            float4 kv, qv;
            kv = __ldg(kp + lane);        qv = qsm[lane];
            p0 = kv.x*qv.x + kv.y*qv.y + kv.z*qv.z + kv.w*qv.w;
            kv = __ldg(kp + 32 + lane);   qv = qsm[32 + lane];
            p1 = kv.x*qv.x + kv.y*qv.y + kv.z*qv.z + kv.w*qv.w;
            kv = __ldg(kp + 64 + lane);   qv = qsm[64 + lane];
            p2 = kv.x*qv.x + kv.y*qv.y + kv.z*qv.z + kv.w*qv.w;
            kv = __ldg(kp + 96 + lane);   qv = qsm[96 + lane];
            p3 = kv.x*qv.x + kv.y*qv.y + kv.z*qv.z + kv.w*qv.w;
        }
        // 2 butterfly levels on all 4 regs -> 4-lane groups done
        p0 += __shfl_xor_sync(0xffffffffu, p0, 1);
        p1 += __shfl_xor_sync(0xffffffffu, p1, 1);
        p2 += __shfl_xor_sync(0xffffffffu, p2, 1);
        p3 += __shfl_xor_sync(0xffffffffu, p3, 1);
        p0 += __shfl_xor_sync(0xffffffffu, p0, 2);
        p1 += __shfl_xor_sync(0xffffffffu, p1, 2);
        p2 += __shfl_xor_sync(0xffffffffu, p2, 2);
        p3 += __shfl_xor_sync(0xffffffffu, p3, 2);
        // fold: lane&3 selects which partial this lane carries
        int sel = lane & 3;
        float v = (sel == 0) ? p0 : (sel == 1) ? p1 : (sel == 2) ? p2 : p3;
        v += __shfl_xor_sync(0xffffffffu, v, 4);
        v += __shfl_xor_sync(0xffffffffu, v, 8);
        // lane l (l&15 < 4): v = full 16-lane dot for head 2*(l&3) + (l>>4)
        if ((lane & 15) < 4)
            dots[s * 8 + 2 * (lane & 3) + (lane >> 4)] = v;
    }
    __syncthreads();

    if (t < 8) {
        float m = -INFINITY, sum = 0.f;
        for (int s = 0; s < U_; s++) {
            float v = dots[s * 8 + t];
            m = fmaxf(m, v);
            sum += v;
        }
        g_M[(b * 8 + t) * L_ + q] = m - sum * (1.0f / (float)L_);
    }
}

// ---------------- Kernel C: radix-select top-45 per (b,h) ----------------
// Exact threshold via 4x8-bit digit passes on sortable uints, then collect
// strict candidates + index-sorted ties; final 45 sorted (value desc, idx asc).
__global__ __launch_bounds__(256) void topk_kernel()
{
    int bh = blockIdx.x;
    int t = threadIdx.x, lane = t & 31, wid = t >> 5;
    __shared__ uint32_t skey[L_];          // 16KB
    __shared__ int hist[256];
    __shared__ int wsum[8];
    __shared__ int sh_need, sh_digit, sh_newneed;
    __shared__ uint32_t sh_prefix;
    __shared__ int nstrict, ntie;
    __shared__ unsigned long long cand[64];
    __shared__ int ties[128];

    for (int i = t; i < L_; i += 256) {
        uint32_t bts = __float_as_uint(g_M[bh * L_ + i]);
        bts ^= (bts >> 31) ? 0xFFFFFFFFu : 0x80000000u;  // ascending-sortable
        skey[i] = bts;
    }
    if (t == 0) { sh_need = U_; sh_prefix = 0; nstrict = 0; ntie = 0; }
    __syncthreads();

    for (int pass = 0; pass < 4; pass++) {
        int shift = 24 - pass * 8;
        uint32_t pmask = (pass == 0) ? 0u : (0xFFFFFFFFu << (shift + 8));
        hist[t] = 0;
        __syncthreads();
        uint32_t pref = sh_prefix;
        for (int i = t; i < L_; i += 256) {
            uint32_t kv = skey[i];
            if ((kv & pmask) == pref)
                atomicAdd(&hist[(kv >> shift) & 0xFF], 1);
        }
        __syncthreads();
        int c = hist[t];
        int s = c;
#pragma unroll
        for (int o = 1; o < 32; o <<= 1) {
            int v = __shfl_down_sync(0xffffffffu, s, o);
            if (lane + o < 32) s += v;
        }
        if (lane == 0) wsum[wid] = s;       // warp total (at lane 0)
        __syncthreads();
        int ws = 0;
        for (int j = wid + 1; j < 8; j++) ws += wsum[j];
        int suffix_incl = s + ws;           // count of digits >= t
        int suffix_excl = suffix_incl - c;  // count of digits >  t
        int need = sh_need;
        if (suffix_excl < need && suffix_incl >= need) {
            sh_digit = t;
            sh_newneed = need - suffix_excl;
        }
        __syncthreads();
        if (t == 0) {
            sh_prefix |= ((uint32_t)sh_digit) << shift;
            sh_need = sh_newneed;
        }
        __syncthreads();
    }
    uint32_t T = sh_prefix;
    int needT = sh_need;                    // ties to take at T

    for (int i = t; i < L_; i += 256) {
        uint32_t kv = skey[i];
        if (kv > T) {
            int p = atomicAdd(&nstrict, 1);
            cand[p] = ((unsigned long long)kv << 32) |
                      (unsigned long long)(L_ - 1 - i);   // larger = smaller idx
        } else if (kv == T) {
            int p = atomicAdd(&ntie, 1);
            if (p < 128) ties[p] = i;
        }
    }
    __syncthreads();
    if (t == 0) {
        int n = nstrict;                    // == U_ - needT
        for (int a = 1; a < n; a++) {       // desc insertion sort
            unsigned long long key = cand[a]; int p = a - 1;
            while (p >= 0 && cand[p] < key) { cand[p+1] = cand[p]; p--; }
            cand[p+1] = key;
        }
        int m = ntie; if (m > 128) m = 128;
        for (int a = 1; a < m; a++) {       // asc insertion sort of tie indices
            int key = ties[a]; int p = a - 1;
            while (p >= 0 && ties[p] > key) { ties[p+1] = ties[p]; p--; }
            ties[p+1] = key;
        }
        for (int a = 0; a < n; a++)
            g_top[bh * U_ + a] = (int)(L_ - 1 - (int)(cand[a] & 0xFFFFFFFFull));
        for (int a = 0; a < needT; a++)
            g_top[bh * U_ + n + a] = ties[a];
    }
}

// ---------------- Kernel D: fused flash (scores + chunk softmax + PV) -----
// grid (16 bh, 32 chunks of 128 keys). 128 threads.
__global__ __launch_bounds__(128) void flash_kernel(
    const float* __restrict__ Q, const float* __restrict__ K,
    const float* __restrict__ V, const int* __restrict__ mask)
{
    int bh = blockIdx.x, ch = blockIdx.y;
    int b = bh >> 3, h = bh & 7;
    int t = threadIdx.x, lane = t & 31, w = t >> 5;   // 4 warps
    __shared__ __align__(16) float qsm[U_ * D_];      // 11.5KB
    __shared__ int qidx[U_];
    __shared__ __align__(16) float S[U_ * SP_];       // 23.8KB
    __shared__ float msm[U_], ssm[U_];
    __shared__ __align__(16) float vsm[32 * D_];      // 8KB

    if (t < U_) qidx[t] = g_top[bh * U_ + t];
    __syncthreads();
    for (int i = t; i < U_ * D_; i += 128) {
        int u = i >> 6, d = i & 63;
        qsm[i] = Q[((b * L_ + qidx[u]) * H_ + h) * D_ + d];
    }
    __syncthreads();

    // ---- scores: thread = one key ----
    int k = ch * FK_ + t;
    const float4* kp  = reinterpret_cast<const float4*>(K + ((b * L_ + k) * H_ + h) * D_);
    const float4* qp4 = reinterpret_cast<const float4*>(qsm);
    float acc[U_];
#pragma unroll
    for (int u = 0; u < U_; u++) acc[u] = 0.f;
    for (int dv = 0; dv < 16; dv++) {
        float4 kv = kp[dv];
#pragma unroll
        for (int u = 0; u < U_; u++) {
            float4 qv = qp4[u * 16 + dv];
            acc[u] += kv.x * qv.x + kv.y * qv.y + kv.z * qv.z + kv.w * qv.w;
        }
    }
    bool valid = (mask[b * L_ + k] != 0);
#pragma unroll
    for (int u = 0; u < U_; u++)
        S[u * SP_ + t] = valid ? acc[u] * 0.125f : -INFINITY;
    __syncthreads();

    // ---- per-u chunk softmax: warp w handles u = w, w+4, ... ----
    for (int u = w; u < U_; u += 4) {
        const float4* Sr = reinterpret_cast<const float4*>(&S[u * SP_]);
        float4 v = Sr[lane];
        float m = fmaxf(fmaxf(v.x, v.y), fmaxf(v.z, v.w));
#pragma unroll
        for (int o = 16; o > 0; o >>= 1) m = fmaxf(m, __shfl_xor_sync(0xffffffffu, m, o));
        float4 e;
        if (m == -INFINITY) { e.x = e.y = e.z = e.w = 0.f; }
        else {
            e.x = __expf(v.x - m); e.y = __expf(v.y - m);
            e.z = __expf(v.z - m); e.w = __expf(v.w - m);
        }
        float s = e.x + e.y + e.z + e.w;
#pragma unroll
        for (int o = 16; o > 0; o >>= 1) s += __shfl_xor_sync(0xffffffffu, s, o);
        reinterpret_cast<float4*>(&S[u * SP_])[lane] = e;
        if (lane == 0) { msm[u] = m; ssm[u] = s; }
    }
    __syncthreads();

    // ---- PV: warp w handles u in [w*12, w*12+12); thread = float2 of d ----
    float2 pacc[12];
#pragma unroll
    for (int j = 0; j < 12; j++) pacc[j] = make_float2(0.f, 0.f);

    for (int sub = 0; sub < 4; sub++) {
        int kk0 = ch * FK_ + sub * 32;
        for (int i = t; i < 32 * D_; i += 128) {
            int kk = i >> 6, d = i & 63;
            vsm[i] = V[((b * L_ + kk0 + kk) * H_ + h) * D_ + d];
        }
        __syncthreads();
        const float2* vs2 = reinterpret_cast<const float2*>(vsm);
        for (int kt = 0; kt < 4; kt++) {          // 8 keys per tile
            float2 vv[8];
#pragma unroll
            for (int j = 0; j < 8; j++) vv[j] = vs2[(kt * 8 + j) * 32 + lane];
#pragma unroll
            for (int j = 0; j < 12; j++) {
                int u = w * 12 + j;
                if (u < U_) {
                    const float4* Sp = reinterpret_cast<const float4*>(
                        &S[u * SP_ + sub * 32 + kt * 8]);
                    float4 p0 = Sp[0], p1 = Sp[1];
                    pacc[j].x += p0.x * vv[0].x; pacc[j].y += p0.x * vv[0].y;
                    pacc[j].x += p0.y * vv[1].x; pacc[j].y += p0.y * vv[1].y;
                    pacc[j].x += p0.z * vv[2].x; pacc[j].y += p0.z * vv[2].y;
                    pacc[j].x += p0.w * vv[3].x; pacc[j].y += p0.w * vv[3].y;
                    pacc[j].x += p1.x * vv[4].x; pacc[j].y += p1.x * vv[4].y;
                    pacc[j].x += p1.y * vv[5].x; pacc[j].y += p1.y * vv[5].y;
                    pacc[j].x += p1.z * vv[6].x; pacc[j].y += p1.z * vv[6].y;
                    pacc[j].x += p1.w * vv[7].x; pacc[j].y += p1.w * vv[7].y;
                }
            }
        }
        __syncthreads();
    }

#pragma unroll
    for (int j = 0; j < 12; j++) {
        int u = w * 12 + j;
        if (u < U_) {
            float2* gp = reinterpret_cast<float2*>(
                g_part + (((size_t)bh * FC_ + ch) * U_ + u) * D_);
            gp[lane] = pacc[j];
        }
    }
    if (t < U_) {
        g_mrow[(bh * FC_ + ch) * U_ + t] = msm[t];
        g_srow[(bh * FC_ + ch) * U_ + t] = ssm[t];
    }
}

// ---------------- Kernel E: combine chunk partials (online-softmax merge) --
__global__ __launch_bounds__(64) void combine_kernel(float* __restrict__ out)
{
    int blk = blockIdx.x;             // bh*45+u
    int bh = blk / U_, u = blk % U_;
    int b = bh >> 3, h = bh & 7;
    int d = threadIdx.x;

    float mt = -INFINITY;
    for (int c = 0; c < FC_; c++)
        mt = fmaxf(mt, g_mrow[(bh * FC_ + c) * U_ + u]);
    float stot = 0.f, acc = 0.f;
    for (int c = 0; c < FC_; c++) {
        float mc = g_mrow[(bh * FC_ + c) * U_ + u];
        float f = (mc == -INFINITY) ? 0.f : __expf(mc - mt);
        stot += g_srow[(bh * FC_ + c) * U_ + u] * f;
        acc  += g_part[(((size_t)bh * FC_ + c) * U_ + u) * D_ + d] * f;
    }
    out[((b * U_ + u) * H_ + h) * D_ + d] = acc / stot;   // (B, u, H, D)
}

// ---------------- launch ----------------
extern "C" void kernel_launch(void* const* d_in, const int* in_sizes, int n_in,
                              void* d_out, int out_size)
{
    const float* Q    = (const float*)d_in[0];
    const float* K    = (const float*)d_in[1];
    const float* V    = (const float*)d_in[2];
    const int*   mask = (const int*)d_in[3];
    float* out = (float*)d_out;

    // JAX partitionable (foldlike) split of key(1)=(0,1):
    //   child i = BOTH output words of threefry((0,1); hi=0, lo=i); randint uses child 1.
    uint32_t k2a, k2b;
    tf2x32(0u, 1u, 0u, 1u, k2a, k2b);

    sample_m_kernel<<<dim3(L_, B_), 384>>>(Q, K, k2a, k2b);
    topk_kernel<<<BH_, 256>>>();
    flash_kernel<<<dim3(BH_, FC_), 128>>>(Q, K, V, mask);
    combine_kernel<<<BH_ * U_, 64>>>(out);
}

// round 14
// speedup vs baseline: 2.2313x; 1.0357x over previous
#include <cuda_runtime.h>
#include <math.h>
#include <stdint.h>

#define B_ 2
#define L_ 4096
#define H_ 8
#define D_ 64
#define U_ 45
#define BH_ (B_*H_)
#define FC_ 32              /* flash key-chunks */
#define FK_ 128             /* keys per chunk */
#define SP_ 132             /* padded S row (floats) */

// ---------------- scratch (static device allocations only) ----------------
__device__ float g_M[BH_*L_];                        // M scores
__device__ int   g_top[BH_*U_];                      // top-45 indices (desc order)
__device__ float g_part[(size_t)BH_*FC_*U_*D_];      // 5.9 MB PV partials
__device__ float g_mrow[BH_*FC_*U_];                 // chunk max
__device__ float g_srow[BH_*FC_*U_];                 // chunk expsum

// ---------------- threefry2x32 (exact JAX replication) ----------------
__host__ __device__ __forceinline__ uint32_t rotl32(uint32_t x, int d) {
    return (x << d) | (x >> (32 - d));
}

__host__ __device__ __forceinline__ void tf2x32(uint32_t k0, uint32_t k1,
                                                uint32_t x0, uint32_t x1,
                                                uint32_t& o0, uint32_t& o1) {
    uint32_t ks2 = k0 ^ k1 ^ 0x1BD11BDAu;
    x0 += k0; x1 += k1;
#define RND(r) { x0 += x1; x1 = rotl32(x1, (r)); x1 ^= x0; }
    RND(13) RND(15) RND(26) RND(6)   x0 += k1;  x1 += ks2 + 1u;
    RND(17) RND(29) RND(16) RND(24)  x0 += ks2; x1 += k0  + 2u;
    RND(13) RND(15) RND(26) RND(6)   x0 += k0;  x1 += k1  + 3u;
    RND(17) RND(29) RND(16) RND(24)  x0 += k1;  x1 += ks2 + 4u;
    RND(13) RND(15) RND(26) RND(6)   x0 += ks2; x1 += k0  + 5u;
#undef RND
    o0 = x0; o1 = x1;
}

// ---------------- Kernel B: sampled M scores (coalesced, warp per (q,s)) ----
__global__ __launch_bounds__(384) void sample_m_kernel(
    const float* __restrict__ Q, const float* __restrict__ K,
    uint32_t k2a, uint32_t k2b)
{
    int q = blockIdx.x, b = blockIdx.y;
    int t = threadIdx.x, lane = t & 31, w = t >> 5;   // 12 warps
    __shared__ __align__(16) float4 qsm[128];         // Q[b,q,:,:]  512 floats
    __shared__ int   idxs[U_];
    __shared__ float dots[U_ * 8];

    if (t < U_) {
        uint32_t o0, o1;
        tf2x32(k2a, k2b, 0u, (uint32_t)(q * U_ + t), o0, o1);
        idxs[t] = (int)((o0 ^ o1) & (L_ - 1));
    }
    if (t < 128)
        qsm[t] = reinterpret_cast<const float4*>(Q)[(size_t)(b * L_ + q) * 128 + t];
    __syncthreads();

    for (int s = w; s < U_; s += 12) {
        int kr = idxs[s];
        const float4* kp = reinterpret_cast<const float4*>(K) + (size_t)(b * L_ + kr) * 128;
        float p0, p1, p2, p3;
        {
            float4 kv, qv;
            kv = __ldg(kp + lane);        qv = qsm[lane];
            p0 = kv.x*qv.x + kv.y*qv.y + kv.z*qv.z + kv.w*qv.w;
            kv = __ldg(kp + 32 + lane);   qv = qsm[32 + lane];
            p1 = kv.x*qv.x + kv.y*qv.y + kv.z*qv.z + kv.w*qv.w;
            kv = __ldg(kp + 64 + lane);   qv = qsm[64 + lane];
            p2 = kv.x*qv.x + kv.y*qv.y + kv.z*qv.z + kv.w*qv.w;
            kv = __ldg(kp + 96 + lane);   qv = qsm[96 + lane];
            p3 = kv.x*qv.x + kv.y*qv.y + kv.z*qv.z + kv.w*qv.w;
        }
        p0 += __shfl_xor_sync(0xffffffffu, p0, 1);
        p1 += __shfl_xor_sync(0xffffffffu, p1, 1);
        p2 += __shfl_xor_sync(0xffffffffu, p2, 1);
        p3 += __shfl_xor_sync(0xffffffffu, p3, 1);
        p0 += __shfl_xor_sync(0xffffffffu, p0, 2);
        p1 += __shfl_xor_sync(0xffffffffu, p1, 2);
        p2 += __shfl_xor_sync(0xffffffffu, p2, 2);
        p3 += __shfl_xor_sync(0xffffffffu, p3, 2);
        int sel = lane & 3;
        float v = (sel == 0) ? p0 : (sel == 1) ? p1 : (sel == 2) ? p2 : p3;
        v += __shfl_xor_sync(0xffffffffu, v, 4);
        v += __shfl_xor_sync(0xffffffffu, v, 8);
        if ((lane & 15) < 4)
            dots[s * 8 + 2 * (lane & 3) + (lane >> 4)] = v;
    }
    __syncthreads();

    if (t < 8) {
        float m = -INFINITY, sum = 0.f;
        for (int s = 0; s < U_; s++) {
            float v = dots[s * 8 + t];
            m = fmaxf(m, v);
            sum += v;
        }
        g_M[(b * 8 + t) * L_ + q] = m - sum * (1.0f / (float)L_);
    }
}

// ---------------- Kernel C: radix-select top-45 per (b,h) ----------------
__global__ __launch_bounds__(256) void topk_kernel()
{
    int bh = blockIdx.x;
    int t = threadIdx.x, lane = t & 31, wid = t >> 5;
    __shared__ uint32_t skey[L_];          // 16KB
    __shared__ int hist[256];
    __shared__ int wsum[8];
    __shared__ int sh_need, sh_digit, sh_newneed;
    __shared__ uint32_t sh_prefix;
    __shared__ int nstrict, ntie;
    __shared__ unsigned long long cand[64];
    __shared__ int ties[128];

    for (int i = t; i < L_; i += 256) {
        uint32_t bts = __float_as_uint(g_M[bh * L_ + i]);
        bts ^= (bts >> 31) ? 0xFFFFFFFFu : 0x80000000u;  // ascending-sortable
        skey[i] = bts;
    }
    if (t == 0) { sh_need = U_; sh_prefix = 0; nstrict = 0; ntie = 0; }
    __syncthreads();

    for (int pass = 0; pass < 4; pass++) {
        int shift = 24 - pass * 8;
        uint32_t pmask = (pass == 0) ? 0u : (0xFFFFFFFFu << (shift + 8));
        hist[t] = 0;
        __syncthreads();
        uint32_t pref = sh_prefix;
        for (int i = t; i < L_; i += 256) {
            uint32_t kv = skey[i];
            if ((kv & pmask) == pref)
                atomicAdd(&hist[(kv >> shift) & 0xFF], 1);
        }
        __syncthreads();
        int c = hist[t];
        int s = c;
#pragma unroll
        for (int o = 1; o < 32; o <<= 1) {
            int v = __shfl_down_sync(0xffffffffu, s, o);
            if (lane + o < 32) s += v;
        }
        if (lane == 0) wsum[wid] = s;
        __syncthreads();
        int ws = 0;
        for (int j = wid + 1; j < 8; j++) ws += wsum[j];
        int suffix_incl = s + ws;
        int suffix_excl = suffix_incl - c;
        int need = sh_need;
        if (suffix_excl < need && suffix_incl >= need) {
            sh_digit = t;
            sh_newneed = need - suffix_excl;
        }
        __syncthreads();
        if (t == 0) {
            sh_prefix |= ((uint32_t)sh_digit) << shift;
            sh_need = sh_newneed;
        }
        __syncthreads();
    }
    uint32_t T = sh_prefix;
    int needT = sh_need;

    for (int i = t; i < L_; i += 256) {
        uint32_t kv = skey[i];
        if (kv > T) {
            int p = atomicAdd(&nstrict, 1);
            cand[p] = ((unsigned long long)kv << 32) |
                      (unsigned long long)(L_ - 1 - i);
        } else if (kv == T) {
            int p = atomicAdd(&ntie, 1);
            if (p < 128) ties[p] = i;
        }
    }
    __syncthreads();
    if (t == 0) {
        int n = nstrict;
        for (int a = 1; a < n; a++) {
            unsigned long long key = cand[a]; int p = a - 1;
            while (p >= 0 && cand[p] < key) { cand[p+1] = cand[p]; p--; }
            cand[p+1] = key;
        }
        int m = ntie; if (m > 128) m = 128;
        for (int a = 1; a < m; a++) {
            int key = ties[a]; int p = a - 1;
            while (p >= 0 && ties[p] > key) { ties[p+1] = ties[p]; p--; }
            ties[p+1] = key;
        }
        for (int a = 0; a < n; a++)
            g_top[bh * U_ + a] = (int)(L_ - 1 - (int)(cand[a] & 0xFFFFFFFFull));
        for (int a = 0; a < needT; a++)
            g_top[bh * U_ + n + a] = ties[a];
    }
}

// ---------------- Kernel D: fused flash (scores + chunk softmax + PV) -----
__global__ __launch_bounds__(128) void flash_kernel(
    const float* __restrict__ Q, const float* __restrict__ K,
    const float* __restrict__ V, const int* __restrict__ mask)
{
    int bh = blockIdx.x, ch = blockIdx.y;
    int b = bh >> 3, h = bh & 7;
    int t = threadIdx.x, lane = t & 31, w = t >> 5;   // 4 warps
    __shared__ __align__(16) float qsm[U_ * D_];      // 11.5KB
    __shared__ int qidx[U_];
    __shared__ __align__(16) float S[U_ * SP_];       // 23.8KB
    __shared__ float msm[U_], ssm[U_];
    __shared__ __align__(16) float vsm[32 * D_];      // 8KB

    if (t < U_) qidx[t] = g_top[bh * U_ + t];
    __syncthreads();
    for (int i = t; i < U_ * D_; i += 128) {
        int u = i >> 6, d = i & 63;
        qsm[i] = Q[((b * L_ + qidx[u]) * H_ + h) * D_ + d];
    }
    __syncthreads();

    int k = ch * FK_ + t;
    const float4* kp  = reinterpret_cast<const float4*>(K + ((b * L_ + k) * H_ + h) * D_);
    const float4* qp4 = reinterpret_cast<const float4*>(qsm);
    float acc[U_];
#pragma unroll
    for (int u = 0; u < U_; u++) acc[u] = 0.f;
    for (int dv = 0; dv < 16; dv++) {
        float4 kv = kp[dv];
#pragma unroll
        for (int u = 0; u < U_; u++) {
            float4 qv = qp4[u * 16 + dv];
            acc[u] += kv.x * qv.x + kv.y * qv.y + kv.z * qv.z + kv.w * qv.w;
        }
    }
    bool valid = (mask[b * L_ + k] != 0);
#pragma unroll
    for (int u = 0; u < U_; u++)
        S[u * SP_ + t] = valid ? acc[u] * 0.125f : -INFINITY;
    __syncthreads();

    for (int u = w; u < U_; u += 4) {
        const float4* Sr = reinterpret_cast<const float4*>(&S[u * SP_]);
        float4 v = Sr[lane];
        float m = fmaxf(fmaxf(v.x, v.y), fmaxf(v.z, v.w));
#pragma unroll
        for (int o = 16; o > 0; o >>= 1) m = fmaxf(m, __shfl_xor_sync(0xffffffffu, m, o));
        float4 e;
        if (m == -INFINITY) { e.x = e.y = e.z = e.w = 0.f; }
        else {
            e.x = __expf(v.x - m); e.y = __expf(v.y - m);
            e.z = __expf(v.z - m); e.w = __expf(v.w - m);
        }
        float s = e.x + e.y + e.z + e.w;
#pragma unroll
        for (int o = 16; o > 0; o >>= 1) s += __shfl_xor_sync(0xffffffffu, s, o);
        reinterpret_cast<float4*>(&S[u * SP_])[lane] = e;
        if (lane == 0) { msm[u] = m; ssm[u] = s; }
    }
    __syncthreads();

    float2 pacc[12];
#pragma unroll
    for (int j = 0; j < 12; j++) pacc[j] = make_float2(0.f, 0.f);

    for (int sub = 0; sub < 4; sub++) {
        int kk0 = ch * FK_ + sub * 32;
        for (int i = t; i < 32 * D_; i += 128) {
            int kk = i >> 6, d = i & 63;
            vsm[i] = V[((b * L_ + kk0 + kk) * H_ + h) * D_ + d];
        }
        __syncthreads();
        const float2* vs2 = reinterpret_cast<const float2*>(vsm);
        for (int kt = 0; kt < 4; kt++) {
            float2 vv[8];
#pragma unroll
            for (int j = 0; j < 8; j++) vv[j] = vs2[(kt * 8 + j) * 32 + lane];
#pragma unroll
            for (int j = 0; j < 12; j++) {
                int u = w * 12 + j;
                if (u < U_) {
                    const float4* Sp = reinterpret_cast<const float4*>(
                        &S[u * SP_ + sub * 32 + kt * 8]);
                    float4 p0 = Sp[0], p1 = Sp[1];
                    pacc[j].x += p0.x * vv[0].x; pacc[j].y += p0.x * vv[0].y;
                    pacc[j].x += p0.y * vv[1].x; pacc[j].y += p0.y * vv[1].y;
                    pacc[j].x += p0.z * vv[2].x; pacc[j].y += p0.z * vv[2].y;
                    pacc[j].x += p0.w * vv[3].x; pacc[j].y += p0.w * vv[3].y;
                    pacc[j].x += p1.x * vv[4].x; pacc[j].y += p1.x * vv[4].y;
                    pacc[j].x += p1.y * vv[5].x; pacc[j].y += p1.y * vv[5].y;
                    pacc[j].x += p1.z * vv[6].x; pacc[j].y += p1.z * vv[6].y;
                    pacc[j].x += p1.w * vv[7].x; pacc[j].y += p1.w * vv[7].y;
                }
            }
        }
        __syncthreads();
    }

#pragma unroll
    for (int j = 0; j < 12; j++) {
        int u = w * 12 + j;
        if (u < U_) {
            float2* gp = reinterpret_cast<float2*>(
                g_part + (((size_t)bh * FC_ + ch) * U_ + u) * D_);
            gp[lane] = pacc[j];
        }
    }
    if (t < U_) {
        g_mrow[(bh * FC_ + ch) * U_ + t] = msm[t];
        g_srow[(bh * FC_ + ch) * U_ + t] = ssm[t];
    }
}

// ---------------- Kernel E: combine chunk partials (parallel v2) ----------
// Block per (bh,u), 256 threads = 4 chunk-groups x 64 d. Warp 0 computes the
// global max + rescaled expsum over all 32 chunks in one shfl pass; the
// chunk-group accumulation gives 8 independent coalesced loads per thread.
__global__ __launch_bounds__(256) void combine_kernel(float* __restrict__ out)
{
    int blk = blockIdx.x;             // bh*45+u
    int bh = blk / U_, u = blk % U_;
    int b = bh >> 3, h = bh & 7;
    int t = threadIdx.x;
    int d = t & 63, cg = t >> 6;      // 4 chunk groups
    __shared__ float racc[256];
    __shared__ float sh_mt, sh_stot;

    if (t < 32) {                     // FC_ == 32
        float mv = g_mrow[(bh * FC_ + t) * U_ + u];
        float m = mv;
#pragma unroll
        for (int o = 16; o > 0; o >>= 1) m = fmaxf(m, __shfl_xor_sync(0xffffffffu, m, o));
        float f = (mv == -INFINITY) ? 0.f : __expf(mv - m);
        float s = g_srow[(bh * FC_ + t) * U_ + u] * f;
#pragma unroll
        for (int o = 16; o > 0; o >>= 1) s += __shfl_xor_sync(0xffffffffu, s, o);
        if (t == 0) { sh_mt = m; sh_stot = s; }
    }
    __syncthreads();
    float mt = sh_mt;

    float acc = 0.f;
#pragma unroll
    for (int c0 = 0; c0 < FC_ / 4; c0++) {
        int c = cg * (FC_ / 4) + c0;  // contiguous group -> preserves sum order per cg
        float mc = g_mrow[(bh * FC_ + c) * U_ + u];
        float f = (mc == -INFINITY) ? 0.f : __expf(mc - mt);
        acc += g_part[(((size_t)bh * FC_ + c) * U_ + u) * D_ + d] * f;
    }
    racc[t] = acc;
    __syncthreads();

    if (t < 64) {
        float s = ((racc[t] + racc[t + 64]) + (racc[t + 128] + racc[t + 192]));
        out[((b * U_ + u) * H_ + h) * D_ + d] = s / sh_stot;   // (B, u, H, D)
    }
}

// ---------------- launch ----------------
extern "C" void kernel_launch(void* const* d_in, const int* in_sizes, int n_in,
                              void* d_out, int out_size)
{
    const float* Q    = (const float*)d_in[0];
    const float* K    = (const float*)d_in[1];
    const float* V    = (const float*)d_in[2];
    const int*   mask = (const int*)d_in[3];
    float* out = (float*)d_out;

    // JAX partitionable (foldlike) split of key(1)=(0,1):
    //   child i = BOTH output words of threefry((0,1); hi=0, lo=i); randint uses child 1.
    uint32_t k2a, k2b;
    tf2x32(0u, 1u, 0u, 1u, k2a, k2b);

    sample_m_kernel<<<dim3(L_, B_), 384>>>(Q, K, k2a, k2b);
    topk_kernel<<<BH_, 256>>>();
    flash_kernel<<<dim3(BH_, FC_), 128>>>(Q, K, V, mask);
    combine_kernel<<<BH_ * U_, 256>>>(out);
}